// round 7
// baseline (speedup 1.0000x reference)
#include <cuda_runtime.h>
#include <cuda_bf16.h>
#include <cstdint>

// Problem constants
#define B_    4
#define H_    16
#define N_    8192
#define DE    64
#define TM    128
#define EPSV  1e-10f
#define KSPLIT 32

#define KV_OFF   ((long long)B_ * H_ * N_ * DE)
#define NORM_OFF (KV_OFF + (long long)B_ * H_ * DE * DE)

// bf16 tiles, row stride 72 elements (144 B) -> conflict-free ldmatrix
#define LDBB  144

// ---- fw_q smem layout ----
#define Q_QHI  0
#define Q_PHI  18432
#define Q_PLO  27648
#define Q_TOTAL 36864          // -> 3 CTAs/SM (reg-capped)

// ---- fw_k smem layout ----
#define K_KHI  0
#define K_KLO  18432
#define K_VHI  36864
#define K_VLO  55296
#define K_PHI  73728
#define K_PLO  82944
#define K_TOTAL 92160          // -> 2 CTAs/SM

union F4 { float4 v; float a[4]; };

// ---------------------------------------------------------------------------
__device__ __forceinline__ uint32_t smem_u32(const void* p) {
    uint32_t a;
    asm("{ .reg .u64 t; cvta.to.shared.u64 t, %1; cvt.u32.u64 %0, t; }"
        : "=r"(a) : "l"(p));
    return a;
}
__device__ __forceinline__ void ldsm4(uint32_t* r, uint32_t addr) {
    asm("ldmatrix.sync.aligned.m8n8.x4.shared.b16 {%0,%1,%2,%3}, [%4];"
        : "=r"(r[0]), "=r"(r[1]), "=r"(r[2]), "=r"(r[3]) : "r"(addr) : "memory");
}
__device__ __forceinline__ void ldsm4t(uint32_t* r, uint32_t addr) {
    asm("ldmatrix.sync.aligned.m8n8.x4.trans.shared.b16 {%0,%1,%2,%3}, [%4];"
        : "=r"(r[0]), "=r"(r[1]), "=r"(r[2]), "=r"(r[3]) : "r"(addr) : "memory");
}
__device__ __forceinline__ void ldsm2t(uint32_t* r, uint32_t addr) {
    asm("ldmatrix.sync.aligned.m8n8.x2.trans.shared.b16 {%0,%1}, [%2];"
        : "=r"(r[0]), "=r"(r[1]) : "r"(addr) : "memory");
}
__device__ __forceinline__ void mma16816(float* c, const uint32_t* a, const uint32_t* b) {
    asm("mma.sync.aligned.m16n8k16.row.col.f32.bf16.bf16.f32 "
        "{%0,%1,%2,%3}, {%4,%5,%6,%7}, {%8,%9}, {%0,%1,%2,%3};"
        : "+f"(c[0]), "+f"(c[1]), "+f"(c[2]), "+f"(c[3])
        : "r"(a[0]), "r"(a[1]), "r"(a[2]), "r"(a[3]), "r"(b[0]), "r"(b[1]));
}
__device__ __forceinline__ void pf_l2(const float* p) {
    asm("prefetch.global.L2 [%0];" :: "l"(p));
}
__device__ __forceinline__ float elu1(float x) {
    return x > 0.f ? x + 1.f : __expf(x);
}
__device__ __forceinline__ unsigned packbf(float x, float y) {
    __nv_bfloat162 t(__float2bfloat16(x), __float2bfloat16(y));
    return *reinterpret_cast<unsigned*>(&t);
}
__device__ __forceinline__ void splitf(float x, float& hi, float& lo) {
    hi = __bfloat162float(__float2bfloat16(x));
    lo = x - hi;
}

// ---------------------------------------------------------------------------
__global__ void fw_init(const float* __restrict__ pkv,
                        const float* __restrict__ pnorm,
                        float* __restrict__ dout) {
    int i = blockIdx.x * blockDim.x + threadIdx.x;
    if (i < B_ * H_ * DE * DE) dout[KV_OFF + i]   = pkv[i];
    if (i < B_ * H_ * DE)      dout[NORM_OFF + i] = pnorm[i];
}

// ---------------------------------------------------------------------------
// Shared helper: stage pkv hi/lo + norm column-64 into smem.
// ---------------------------------------------------------------------------
__device__ __forceinline__ void stage_pkv(char* smc, int phi, int plo,
                                          const float* pg, const float* pn,
                                          int tid) {
    for (int i = tid; i < DE * DE; i += 256) {
        int d = i >> 6, e = i & 63;
        float hi, lo; splitf(pg[i], hi, lo);
        *(__nv_bfloat16*)(smc + phi + d * LDBB + e * 2) = __float2bfloat16(hi);
        *(__nv_bfloat16*)(smc + plo + d * LDBB + e * 2) = __float2bfloat16(lo);
    }
    for (int i = tid; i < DE * 8; i += 256) {
        int d = i >> 3, c = 64 + (i & 7);
        float hi = 0.f, lo = 0.f;
        if (c == 64) splitf(pn[d], hi, lo);
        *(__nv_bfloat16*)(smc + phi + d * LDBB + c * 2) = __float2bfloat16(hi);
        *(__nv_bfloat16*)(smc + plo + d * LDBB + c * 2) = __float2bfloat16(lo);
    }
}

// ===========================================================================
// fw_q: out_g = out*gate + retrieve(elu(q)+1)*(1-gate).  One tile per CTA.
// ===========================================================================
__global__ __launch_bounds__(256, 3)
void fw_q(const float* __restrict__ queries,
          const float* __restrict__ outin,
          const float* __restrict__ pkv,
          const float* __restrict__ pnorm,
          const float* __restrict__ hg,
          float* __restrict__ dout)
{
    extern __shared__ char smc[];
    const uint32_t sb = smem_u32(smc);

    const int tid  = threadIdx.x;
    const int lane = tid & 31;
    const int w    = tid >> 5;
    const int R0   = w * 16;
    const int bh   = blockIdx.y;
    const int h    = bh & (H_ - 1);
    const int row0 = blockIdx.x * TM;

    const float gate  = 1.f / (1.f + __expf(-hg[h]));
    const float gate1 = 1.f - gate;
    const long long baseg = (long long)bh * N_ * DE;

    stage_pkv(smc, Q_PHI, Q_PLO, pkv + (long long)bh * DE * DE, pnorm + bh * DE, tid);

    const int c15 = tid & 15;
    // Phase A: q -> elu -> bf16(hi) -> smem; prefetch out rows into L2
    #pragma unroll
    for (int it = 0; it < 8; it++) {
        int row = (tid >> 4) + it * 16;
        long long g = baseg + (long long)(row0 + row) * DE + 4 * c15;
        F4 q4; q4.v = *(const float4*)(queries + g);
        #pragma unroll
        for (int j = 0; j < 4; j++) q4.a[j] = elu1(q4.a[j]);
        *(uint2*)(smc + Q_QHI + (uint32_t)row * LDBB + 8 * c15) =
            make_uint2(packbf(q4.a[0], q4.a[1]), packbf(q4.a[2], q4.a[3]));
        if (it == 0) pf_l2(outin + g);
    }
    __syncthreads();

    const uint32_t aoff   = (uint32_t)(lane & 15) * LDBB + ((lane & 16) ? 16 : 0);
    const uint32_t btoff  = (uint32_t)(lane & 15) * LDBB;
    const uint32_t btoff4 = btoff + ((lane & 16) ? 16 : 0);
    const int g8 = lane >> 2, tig = lane & 3, srcl = (lane >> 2) << 2;

    float numq[8][4];
    #pragma unroll
    for (int i = 0; i < 8; i++)
        #pragma unroll
        for (int j = 0; j < 4; j++) numq[i][j] = 0.f;
    float dq[4] = {0.f, 0.f, 0.f, 0.f};

    #pragma unroll
    for (int ks = 0; ks < 4; ks++) {
        uint32_t aq[4];
        ldsm4(aq, sb + Q_QHI + (uint32_t)R0 * LDBB + ks * 32 + aoff);
        #pragma unroll
        for (int p = 0; p < 4; p++) {
            uint32_t bhf[4], blf[4];
            ldsm4t(bhf, sb + Q_PHI + (uint32_t)(ks * 16) * LDBB + p * 32 + btoff4);
            ldsm4t(blf, sb + Q_PLO + (uint32_t)(ks * 16) * LDBB + p * 32 + btoff4);
            mma16816(numq[2*p],   aq, bhf);
            mma16816(numq[2*p],   aq, blf);
            mma16816(numq[2*p+1], aq, bhf + 2);
            mma16816(numq[2*p+1], aq, blf + 2);
        }
        uint32_t dh[2], dl[2];
        ldsm2t(dh, sb + Q_PHI + (uint32_t)(ks * 16) * LDBB + 128 + btoff);
        ldsm2t(dl, sb + Q_PLO + (uint32_t)(ks * 16) * LDBB + 128 + btoff);
        mma16816(dq, aq, dh);
        mma16816(dq, aq, dl);
    }

    // out_g epilogue
    {
        float r0v = __frcp_rn(fmaxf(dq[0], EPSV));
        float r2v = __frcp_rn(fmaxf(dq[2], EPSV));
        float rqa = __shfl_sync(0xffffffffu, r0v, srcl) * gate1;
        float rqb = __shfl_sync(0xffffffffu, r2v, srcl) * gate1;
        const int ra = R0 + g8, rb = ra + 8;
        const long long gra = baseg + (long long)(row0 + ra) * DE;
        const long long grb = baseg + (long long)(row0 + rb) * DE;
        #pragma unroll
        for (int nb = 0; nb < 8; nb++) {
            int col = nb * 8 + tig * 2;
            float2 oa = *(const float2*)(outin + gra + col);
            float2 ob = *(const float2*)(outin + grb + col);
            float2 ga, gb;
            ga.x = oa.x * gate + numq[nb][0] * rqa;
            ga.y = oa.y * gate + numq[nb][1] * rqa;
            gb.x = ob.x * gate + numq[nb][2] * rqb;
            gb.y = ob.y * gate + numq[nb][3] * rqb;
            *(float2*)(dout + gra + col) = ga;
            *(float2*)(dout + grb + col) = gb;
        }
    }
}

// ===========================================================================
// fw_k: delta-rule v', new_kv += k^T v', new_norm += sum k (via col 64 of v')
// ===========================================================================
__global__ __launch_bounds__(256, 2)
void fw_k(const float* __restrict__ keys,
          const float* __restrict__ values,
          const float* __restrict__ pkv,
          const float* __restrict__ pnorm,
          float* __restrict__ dout)
{
    extern __shared__ char smc[];
    const uint32_t sb = smem_u32(smc);

    const int tid  = threadIdx.x;
    const int lane = tid & 31;
    const int w    = tid >> 5;
    const int R0   = w * 16;
    const int split = blockIdx.x;
    const int bh    = blockIdx.y;

    const long long baseg = (long long)bh * N_ * DE;
    const int rows_per = N_ / KSPLIT;    // 256
    const int row0 = split * rows_per;
    const int ntiles = rows_per / TM;    // 2

    stage_pkv(smc, K_PHI, K_PLO, pkv + (long long)bh * DE * DE, pnorm + bh * DE, tid);

    // v' tile: constant cols 64-71 (col 64 = 1.0 -> norm rides in GEMM2)
    for (int i = tid; i < TM * 8; i += 256) {
        int row = i >> 3, c = 64 + (i & 7);
        *(__nv_bfloat16*)(smc + K_VHI + row * LDBB + c * 2) =
            __float2bfloat16(c == 64 ? 1.f : 0.f);
        *(__nv_bfloat16*)(smc + K_VLO + row * LDBB + c * 2) = __float2bfloat16(0.f);
    }

    const uint32_t aoff   = (uint32_t)(lane & 15) * LDBB + ((lane & 16) ? 16 : 0);
    const uint32_t atoff  = (uint32_t)((lane & 7) + ((lane & 16) ? 8 : 0)) * LDBB
                          + ((lane & 8) ? 16 : 0);
    const uint32_t btoff  = (uint32_t)(lane & 15) * LDBB;
    const uint32_t btoff4 = btoff + ((lane & 16) ? 16 : 0);
    const int g8 = lane >> 2, tig = lane & 3, srcl = (lane >> 2) << 2;

    // GEMM2 split: warps 0-3 / 4-7 share d-rows, cover e 0-31 / 32-63 (+norm on 4-7)
    const int dR   = (w & 3) * 16;
    const int eoff = (w >> 2) * 32;

    float acc2[4][4];
    #pragma unroll
    for (int i = 0; i < 4; i++)
        #pragma unroll
        for (int j = 0; j < 4; j++) acc2[i][j] = 0.f;
    float accn[4] = {0.f, 0.f, 0.f, 0.f};

    const int c15 = tid & 15;

    for (int t = 0; t < ntiles; t++) {
        const int t0 = t * TM;

        // ---- Phase A: load k; elu; bf16 split -> smem; L2-prefetch values ---
        #pragma unroll
        for (int it = 0; it < 8; it++) {
            int row = (tid >> 4) + it * 16;
            long long g = baseg + (long long)(row0 + t0 + row) * DE + 4 * c15;
            F4 k4; k4.v = *(const float4*)(keys + g);
            #pragma unroll
            for (int j = 0; j < 4; j++) k4.a[j] = elu1(k4.a[j]);
            float h0,l0,h1,l1,h2,l2,h3,l3;
            splitf(k4.a[0],h0,l0); splitf(k4.a[1],h1,l1);
            splitf(k4.a[2],h2,l2); splitf(k4.a[3],h3,l3);
            uint32_t off = (uint32_t)row * LDBB + 8 * c15;
            *(uint2*)(smc + K_KHI + off) = make_uint2(packbf(h0,h1), packbf(h2,h3));
            *(uint2*)(smc + K_KLO + off) = make_uint2(packbf(l0,l1), packbf(l2,l3));
            if (it == 0) pf_l2(values + g);
        }
        __syncthreads();

        // ---- GEMM1-k: numer_k (3-term) + denom (col 64) --------------------
        float numk[8][4];
        #pragma unroll
        for (int i = 0; i < 8; i++)
            #pragma unroll
            for (int j = 0; j < 4; j++) numk[i][j] = 0.f;
        float dk[4] = {0.f, 0.f, 0.f, 0.f};

        #pragma unroll
        for (int ks = 0; ks < 4; ks++) {
            uint32_t ah[4], al[4];
            ldsm4(ah, sb + K_KHI + (uint32_t)R0 * LDBB + ks * 32 + aoff);
            ldsm4(al, sb + K_KLO + (uint32_t)R0 * LDBB + ks * 32 + aoff);
            #pragma unroll
            for (int p = 0; p < 4; p++) {
                uint32_t bhf[4], blf[4];
                ldsm4t(bhf, sb + K_PHI + (uint32_t)(ks * 16) * LDBB + p * 32 + btoff4);
                ldsm4t(blf, sb + K_PLO + (uint32_t)(ks * 16) * LDBB + p * 32 + btoff4);
                mma16816(numk[2*p],   ah, bhf);
                mma16816(numk[2*p],   ah, blf);
                mma16816(numk[2*p],   al, bhf);
                mma16816(numk[2*p+1], ah, bhf + 2);
                mma16816(numk[2*p+1], ah, blf + 2);
                mma16816(numk[2*p+1], al, bhf + 2);
            }
            uint32_t dh[2], dl[2];
            ldsm2t(dh, sb + K_PHI + (uint32_t)(ks * 16) * LDBB + 128 + btoff);
            ldsm2t(dl, sb + K_PLO + (uint32_t)(ks * 16) * LDBB + 128 + btoff);
            mma16816(dk, ah, dh);
            mma16816(dk, ah, dl);
            mma16816(dk, al, dh);
        }

        // ---- v' = values - numer_k/denom_k -> smem (bf16 split) ------------
        {
            float r0v = __frcp_rn(fmaxf(dk[0], EPSV));
            float r2v = __frcp_rn(fmaxf(dk[2], EPSV));
            float rka = __shfl_sync(0xffffffffu, r0v, srcl);
            float rkb = __shfl_sync(0xffffffffu, r2v, srcl);
            const int ra = R0 + g8, rb = ra + 8;
            const long long gra = baseg + (long long)(row0 + t0 + ra) * DE;
            const long long grb = baseg + (long long)(row0 + t0 + rb) * DE;
            #pragma unroll
            for (int nb = 0; nb < 8; nb++) {
                int col = nb * 8 + tig * 2;
                float2 va = *(const float2*)(values + gra + col);
                float2 vb = *(const float2*)(values + grb + col);
                float n0 = va.x - numk[nb][0] * rka;
                float n1 = va.y - numk[nb][1] * rka;
                float n2 = vb.x - numk[nb][2] * rkb;
                float n3 = vb.y - numk[nb][3] * rkb;
                float h0,l0,h1,l1,h2,l2,h3,l3;
                splitf(n0,h0,l0); splitf(n1,h1,l1);
                splitf(n2,h2,l2); splitf(n3,h3,l3);
                uint32_t oa = (uint32_t)ra * LDBB + col * 2;
                uint32_t ob = (uint32_t)rb * LDBB + col * 2;
                *(uint32_t*)(smc + K_VHI + oa) = packbf(h0, h1);
                *(uint32_t*)(smc + K_VLO + oa) = packbf(l0, l1);
                *(uint32_t*)(smc + K_VHI + ob) = packbf(h2, h3);
                *(uint32_t*)(smc + K_VLO + ob) = packbf(l2, l3);
            }
        }
        __syncthreads();

        // ---- GEMM2: new_kv += k^T v' (3-term); norm via col 64 -------------
        #pragma unroll
        for (int ks = 0; ks < 8; ks++) {
            uint32_t ah[4], al[4];
            ldsm4t(ah, sb + K_KHI + (uint32_t)(ks * 16) * LDBB + dR * 2 + atoff);
            ldsm4t(al, sb + K_KLO + (uint32_t)(ks * 16) * LDBB + dR * 2 + atoff);
            #pragma unroll
            for (int p = 0; p < 2; p++) {
                uint32_t bhf[4], blf[4];
                uint32_t bcol = (uint32_t)eoff * 2 + p * 32;
                ldsm4t(bhf, sb + K_VHI + (uint32_t)(ks * 16) * LDBB + bcol + btoff4);
                ldsm4t(blf, sb + K_VLO + (uint32_t)(ks * 16) * LDBB + bcol + btoff4);
                mma16816(acc2[2*p],   ah, bhf);
                mma16816(acc2[2*p],   ah, blf);
                mma16816(acc2[2*p],   al, bhf);
                mma16816(acc2[2*p+1], ah, bhf + 2);
                mma16816(acc2[2*p+1], ah, blf + 2);
                mma16816(acc2[2*p+1], al, bhf + 2);
            }
            if (w >= 4) {   // norm block: v'[.,64]=1 (hi), lo=0 -> exact sum k
                uint32_t dh[2];
                ldsm2t(dh, sb + K_VHI + (uint32_t)(ks * 16) * LDBB + 128 + btoff);
                mma16816(accn, ah, dh);
                mma16816(accn, al, dh);
            }
        }
        __syncthreads();
    }

    // ---- Epilogue: merge new_kv / new_norm ---------------------------------
    float* kvo = dout + KV_OFF + (long long)bh * DE * DE;
    #pragma unroll
    for (int nb = 0; nb < 4; nb++) {
        int col = eoff + nb * 8 + tig * 2;
        atomicAdd(&kvo[(dR + g8) * DE + col],     acc2[nb][0]);
        atomicAdd(&kvo[(dR + g8) * DE + col + 1], acc2[nb][1]);
        atomicAdd(&kvo[(dR + g8 + 8) * DE + col],     acc2[nb][2]);
        atomicAdd(&kvo[(dR + g8 + 8) * DE + col + 1], acc2[nb][3]);
    }
    if (w >= 4 && tig == 0) {
        float* no = dout + NORM_OFF + (long long)bh * DE;
        atomicAdd(&no[dR + g8],     accn[0]);
        atomicAdd(&no[dR + g8 + 8], accn[2]);
    }
}

// ---------------------------------------------------------------------------
extern "C" void kernel_launch(void* const* d_in, const int* in_sizes, int n_in,
                              void* d_out, int out_size) {
    const float* keys    = (const float*)d_in[0];
    const float* values  = (const float*)d_in[1];
    const float* queries = (const float*)d_in[2];
    const float* outin   = (const float*)d_in[3];
    const float* pkv     = (const float*)d_in[4];
    const float* pnorm   = (const float*)d_in[5];
    const float* hg      = (const float*)d_in[6];
    float* dout = (float*)d_out;

    cudaFuncSetAttribute(fw_q, cudaFuncAttributeMaxDynamicSharedMemorySize, Q_TOTAL);
    cudaFuncSetAttribute(fw_k, cudaFuncAttributeMaxDynamicSharedMemorySize, K_TOTAL);

    fw_init<<<(B_ * H_ * DE * DE + 255) / 256, 256>>>(pkv, pnorm, dout);

    dim3 gk(KSPLIT, B_ * H_);
    fw_k<<<gk, 256, K_TOTAL>>>(keys, values, pkv, pnorm, dout);

    dim3 gq(N_ / TM, B_ * H_);
    fw_q<<<gq, 256, Q_TOTAL>>>(queries, outin, pkv, pnorm, hg, dout);
}

// round 8
// speedup vs baseline: 1.5023x; 1.5023x over previous
#include <cuda_runtime.h>
#include <cuda_bf16.h>
#include <cstdint>

// Problem constants
#define B_    4
#define H_    16
#define N_    8192
#define DE    64
#define SPLIT 16
#define TM    64
#define EPSV  1e-10f

#define KV_OFF   ((long long)B_ * H_ * N_ * DE)
#define NORM_OFF (KV_OFF + (long long)B_ * H_ * DE * DE)

// bf16 tiles, row stride 72 elements (144 B)
#define LDBB  144
#define SM_KHI 0
#define SM_KLO 9216
#define SM_QHI 18432
#define SM_VHI 27648
#define SM_VLO 36864
#define SM_PHI 46080                 // pkv hi [64][72] (col 64 = norm)
#define SM_PLO 55296
#define SMEM_TOTAL 64512             // -> 3 CTAs/SM

union F4 { float4 v; float a[4]; };

// ---------------------------------------------------------------------------
__device__ __forceinline__ uint32_t smem_u32(const void* p) {
    uint32_t a;
    asm("{ .reg .u64 t; cvta.to.shared.u64 t, %1; cvt.u32.u64 %0, t; }"
        : "=r"(a) : "l"(p));
    return a;
}
__device__ __forceinline__ void ldsm4(uint32_t* r, uint32_t addr) {
    asm("ldmatrix.sync.aligned.m8n8.x4.shared.b16 {%0,%1,%2,%3}, [%4];"
        : "=r"(r[0]), "=r"(r[1]), "=r"(r[2]), "=r"(r[3]) : "r"(addr) : "memory");
}
__device__ __forceinline__ void ldsm4t(uint32_t* r, uint32_t addr) {
    asm("ldmatrix.sync.aligned.m8n8.x4.trans.shared.b16 {%0,%1,%2,%3}, [%4];"
        : "=r"(r[0]), "=r"(r[1]), "=r"(r[2]), "=r"(r[3]) : "r"(addr) : "memory");
}
__device__ __forceinline__ void ldsm2t(uint32_t* r, uint32_t addr) {
    asm("ldmatrix.sync.aligned.m8n8.x2.trans.shared.b16 {%0,%1}, [%2];"
        : "=r"(r[0]), "=r"(r[1]) : "r"(addr) : "memory");
}
__device__ __forceinline__ void mma16816(float* c, const uint32_t* a, const uint32_t* b) {
    asm("mma.sync.aligned.m16n8k16.row.col.f32.bf16.bf16.f32 "
        "{%0,%1,%2,%3}, {%4,%5,%6,%7}, {%8,%9}, {%0,%1,%2,%3};"
        : "+f"(c[0]), "+f"(c[1]), "+f"(c[2]), "+f"(c[3])
        : "r"(a[0]), "r"(a[1]), "r"(a[2]), "r"(a[3]), "r"(b[0]), "r"(b[1]));
}
__device__ __forceinline__ void pf_l2(const float* p) {
    asm("prefetch.global.L2 [%0];" :: "l"(p));
}
__device__ __forceinline__ float elu1(float x) {
    return x > 0.f ? x + 1.f : __expf(x);
}
__device__ __forceinline__ unsigned packbf(float x, float y) {
    __nv_bfloat162 t(__float2bfloat16(x), __float2bfloat16(y));
    return *reinterpret_cast<unsigned*>(&t);
}
__device__ __forceinline__ void splitf(float x, float& hi, float& lo) {
    hi = __bfloat162float(__float2bfloat16(x));
    lo = x - hi;
}

// ---------------------------------------------------------------------------
__global__ void fw_init(const float* __restrict__ pkv,
                        const float* __restrict__ pnorm,
                        float* __restrict__ dout) {
    int i = blockIdx.x * blockDim.x + threadIdx.x;
    if (i < B_ * H_ * DE * DE) dout[KV_OFF + i]   = pkv[i];
    if (i < B_ * H_ * DE)      dout[NORM_OFF + i] = pnorm[i];
}

// ---------------------------------------------------------------------------
__global__ __launch_bounds__(256, 3)
void fw_main(const float* __restrict__ keys,
             const float* __restrict__ values,
             const float* __restrict__ queries,
             const float* __restrict__ outin,
             const float* __restrict__ pkv,
             const float* __restrict__ pnorm,
             const float* __restrict__ hg,
             float* __restrict__ dout)
{
    extern __shared__ char smc[];
    const uint32_t sb = smem_u32(smc);

    const int tid  = threadIdx.x;
    const int lane = tid & 31;
    const int w    = tid >> 5;
    const int w03  = w & 3;            // row/d slice
    const int wh   = w >> 2;           // col half
    const int R0   = w03 * 16;
    const int dR   = w03 * 16;
    const int eoff = wh * 32;
    const int split = blockIdx.x;
    const int bh    = blockIdx.y;
    const int h     = bh & (H_ - 1);

    const float gate  = 1.f / (1.f + __expf(-hg[h]));
    const float gate1 = 1.f - gate;

    // ---- stage pkv (hi/lo bf16) + norm column 64 ---------------------------
    {
        const float* pg = pkv + (long long)bh * DE * DE;
        for (int i = tid; i < DE * DE; i += 256) {
            int d = i >> 6, e = i & 63;
            float hi, lo; splitf(pg[i], hi, lo);
            *(__nv_bfloat16*)(smc + SM_PHI + d * LDBB + e * 2) = __float2bfloat16(hi);
            *(__nv_bfloat16*)(smc + SM_PLO + d * LDBB + e * 2) = __float2bfloat16(lo);
        }
        const float* pn = pnorm + bh * DE;
        for (int i = tid; i < DE * 8; i += 256) {
            int d = i >> 3, c = 64 + (i & 7);
            float hi = 0.f, lo = 0.f;
            if (c == 64) splitf(pn[d], hi, lo);
            *(__nv_bfloat16*)(smc + SM_PHI + d * LDBB + c * 2) = __float2bfloat16(hi);
            *(__nv_bfloat16*)(smc + SM_PLO + d * LDBB + c * 2) = __float2bfloat16(lo);
        }
        // v' tile constant cols 64-71 (col 64 = 1.0 -> new_norm rides GEMM2)
        for (int i = tid; i < TM * 8; i += 256) {
            int row = i >> 3, c = 64 + (i & 7);
            *(__nv_bfloat16*)(smc + SM_VHI + row * LDBB + c * 2) =
                __float2bfloat16(c == 64 ? 1.f : 0.f);
            *(__nv_bfloat16*)(smc + SM_VLO + row * LDBB + c * 2) = __float2bfloat16(0.f);
        }
    }

    const uint32_t aoff   = (uint32_t)(lane & 15) * LDBB + ((lane & 16) ? 16 : 0);
    const uint32_t atoff  = (uint32_t)((lane & 7) + ((lane & 16) ? 8 : 0)) * LDBB
                          + ((lane & 8) ? 16 : 0);
    const uint32_t btoff  = (uint32_t)(lane & 15) * LDBB;
    const uint32_t btoff4 = btoff + ((lane & 16) ? 16 : 0);
    const uint32_t ebyte  = (uint32_t)wh * 64;   // B-col byte base (32 cols)
    const int g8 = lane >> 2, tig = lane & 3, srcl = (lane >> 2) << 2;

    float acc2[4][4];
    #pragma unroll
    for (int i = 0; i < 4; i++)
        #pragma unroll
        for (int j = 0; j < 4; j++) acc2[i][j] = 0.f;
    float accn[4] = {0.f, 0.f, 0.f, 0.f};

    const long long baseg = (long long)bh * N_ * DE;
    const int rows_per = N_ / SPLIT;    // 512
    const int row0 = split * rows_per;
    const int ntiles = rows_per / TM;   // 8
    const int c15 = tid & 15;

    __syncthreads();   // pkv + const cols staged

    for (int t = 0; t < ntiles; t++) {
        const int t0 = t * TM;

        // ---- Phase A: load k,q; elu; bf16 split -> smem --------------------
        #pragma unroll
        for (int it = 0; it < 4; it++) {
            int row = (tid >> 4) + it * 16;
            long long g = baseg + (long long)(row0 + t0 + row) * DE + 4 * c15;
            F4 k4, q4;
            k4.v = *(const float4*)(keys + g);
            q4.v = *(const float4*)(queries + g);
            #pragma unroll
            for (int j = 0; j < 4; j++) { k4.a[j] = elu1(k4.a[j]); q4.a[j] = elu1(q4.a[j]); }
            float h0,l0,h1,l1,h2,l2,h3,l3;
            splitf(k4.a[0],h0,l0); splitf(k4.a[1],h1,l1);
            splitf(k4.a[2],h2,l2); splitf(k4.a[3],h3,l3);
            uint32_t off = (uint32_t)row * LDBB + 8 * c15;
            *(uint2*)(smc + SM_KHI + off) = make_uint2(packbf(h0,h1), packbf(h2,h3));
            *(uint2*)(smc + SM_KLO + off) = make_uint2(packbf(l0,l1), packbf(l2,l3));
            *(uint2*)(smc + SM_QHI + off) =
                make_uint2(packbf(q4.a[0],q4.a[1]), packbf(q4.a[2],q4.a[3]));
        }
        __syncthreads();

        // L2 prefetch next tile
        if (t + 1 < ntiles) {
            long long gp = baseg + (long long)(row0 + t0 + TM + (tid >> 2)) * DE
                         + (tid & 3) * 16;
            pf_l2(keys + gp);
            pf_l2(queries + gp);
            pf_l2(values + gp);
        }

        // ---- GEMM1-k: numer_k (3-term) + denom (col 64) --------------------
        float numk[4][4];
        #pragma unroll
        for (int i = 0; i < 4; i++)
            #pragma unroll
            for (int j = 0; j < 4; j++) numk[i][j] = 0.f;
        float dk[4] = {0.f, 0.f, 0.f, 0.f};

        #pragma unroll
        for (int ks = 0; ks < 4; ks++) {
            uint32_t ah[4], al[4];
            ldsm4(ah, sb + SM_KHI + (uint32_t)R0 * LDBB + ks * 32 + aoff);
            ldsm4(al, sb + SM_KLO + (uint32_t)R0 * LDBB + ks * 32 + aoff);
            #pragma unroll
            for (int p = 0; p < 2; p++) {
                uint32_t bhf[4], blf[4];
                ldsm4t(bhf, sb + SM_PHI + (uint32_t)(ks * 16) * LDBB + ebyte + p * 32 + btoff4);
                ldsm4t(blf, sb + SM_PLO + (uint32_t)(ks * 16) * LDBB + ebyte + p * 32 + btoff4);
                mma16816(numk[2*p],   ah, bhf);
                mma16816(numk[2*p],   ah, blf);
                mma16816(numk[2*p],   al, bhf);
                mma16816(numk[2*p+1], ah, bhf + 2);
                mma16816(numk[2*p+1], ah, blf + 2);
                mma16816(numk[2*p+1], al, bhf + 2);
            }
            uint32_t dh[2], dl[2];
            ldsm2t(dh, sb + SM_PHI + (uint32_t)(ks * 16) * LDBB + 128 + btoff);
            ldsm2t(dl, sb + SM_PLO + (uint32_t)(ks * 16) * LDBB + 128 + btoff);
            mma16816(dk, ah, dh);
            mma16816(dk, ah, dl);
            mma16816(dk, al, dh);
        }

        // ---- v' = values - numer_k/denom_k -> smem (bf16 split) ------------
        {
            float r0v = __frcp_rn(fmaxf(dk[0], EPSV));
            float r2v = __frcp_rn(fmaxf(dk[2], EPSV));
            float rka = __shfl_sync(0xffffffffu, r0v, srcl);
            float rkb = __shfl_sync(0xffffffffu, r2v, srcl);
            const int ra = R0 + g8, rb = ra + 8;
            const long long gra = baseg + (long long)(row0 + t0 + ra) * DE;
            const long long grb = baseg + (long long)(row0 + t0 + rb) * DE;
            #pragma unroll
            for (int nb = 0; nb < 4; nb++) {
                int col = eoff + nb * 8 + tig * 2;
                float2 va = *(const float2*)(values + gra + col);
                float2 vb = *(const float2*)(values + grb + col);
                float n0 = va.x - numk[nb][0] * rka;
                float n1 = va.y - numk[nb][1] * rka;
                float n2 = vb.x - numk[nb][2] * rkb;
                float n3 = vb.y - numk[nb][3] * rkb;
                float h0,l0,h1,l1,h2,l2,h3,l3;
                splitf(n0,h0,l0); splitf(n1,h1,l1);
                splitf(n2,h2,l2); splitf(n3,h3,l3);
                uint32_t oa = (uint32_t)ra * LDBB + col * 2;
                uint32_t ob = (uint32_t)rb * LDBB + col * 2;
                *(uint32_t*)(smc + SM_VHI + oa) = packbf(h0, h1);
                *(uint32_t*)(smc + SM_VLO + oa) = packbf(l0, l1);
                *(uint32_t*)(smc + SM_VHI + ob) = packbf(h2, h3);
                *(uint32_t*)(smc + SM_VLO + ob) = packbf(l2, l3);
            }
        }

        // ---- GEMM1-q: numer_q (1-term; gate1 ~ 4.5e-5 masks bf16 error) ----
        float numq[4][4];
        #pragma unroll
        for (int i = 0; i < 4; i++)
            #pragma unroll
            for (int j = 0; j < 4; j++) numq[i][j] = 0.f;
        float dq[4] = {0.f, 0.f, 0.f, 0.f};
        #pragma unroll
        for (int ks = 0; ks < 4; ks++) {
            uint32_t aq[4];
            ldsm4(aq, sb + SM_QHI + (uint32_t)R0 * LDBB + ks * 32 + aoff);
            #pragma unroll
            for (int p = 0; p < 2; p++) {
                uint32_t bhf[4];
                ldsm4t(bhf, sb + SM_PHI + (uint32_t)(ks * 16) * LDBB + ebyte + p * 32 + btoff4);
                mma16816(numq[2*p],   aq, bhf);
                mma16816(numq[2*p+1], aq, bhf + 2);
            }
            uint32_t dh[2];
            ldsm2t(dh, sb + SM_PHI + (uint32_t)(ks * 16) * LDBB + 128 + btoff);
            mma16816(dq, aq, dh);
        }

        // ---- out_g epilogue (fills time before the v'-ready barrier) -------
        {
            float r0v = __frcp_rn(fmaxf(dq[0], EPSV));
            float r2v = __frcp_rn(fmaxf(dq[2], EPSV));
            float rqa = __shfl_sync(0xffffffffu, r0v, srcl) * gate1;
            float rqb = __shfl_sync(0xffffffffu, r2v, srcl) * gate1;
            const int ra = R0 + g8, rb = ra + 8;
            const long long gra = baseg + (long long)(row0 + t0 + ra) * DE;
            const long long grb = baseg + (long long)(row0 + t0 + rb) * DE;
            #pragma unroll
            for (int nb = 0; nb < 4; nb++) {
                int col = eoff + nb * 8 + tig * 2;
                float2 oa = *(const float2*)(outin + gra + col);
                float2 ob = *(const float2*)(outin + grb + col);
                float2 ga, gb;
                ga.x = oa.x * gate + numq[nb][0] * rqa;
                ga.y = oa.y * gate + numq[nb][1] * rqa;
                gb.x = ob.x * gate + numq[nb][2] * rqb;
                gb.y = ob.y * gate + numq[nb][3] * rqb;
                *(float2*)(dout + gra + col) = ga;
                *(float2*)(dout + grb + col) = gb;
            }
        }
        __syncthreads();   // v' fully written

        // ---- GEMM2: new_kv += k^T v' (3-term); norm via col 64 -------------
        #pragma unroll
        for (int ks = 0; ks < 4; ks++) {
            uint32_t ah[4], al[4];
            ldsm4t(ah, sb + SM_KHI + (uint32_t)(ks * 16) * LDBB + dR * 2 + atoff);
            ldsm4t(al, sb + SM_KLO + (uint32_t)(ks * 16) * LDBB + dR * 2 + atoff);
            #pragma unroll
            for (int p = 0; p < 2; p++) {
                uint32_t bhf[4], blf[4];
                uint32_t bcol = (uint32_t)eoff * 2 + p * 32;
                ldsm4t(bhf, sb + SM_VHI + (uint32_t)(ks * 16) * LDBB + bcol + btoff4);
                ldsm4t(blf, sb + SM_VLO + (uint32_t)(ks * 16) * LDBB + bcol + btoff4);
                mma16816(acc2[2*p],   ah, bhf);
                mma16816(acc2[2*p],   ah, blf);
                mma16816(acc2[2*p],   al, bhf);
                mma16816(acc2[2*p+1], ah, bhf + 2);
                mma16816(acc2[2*p+1], ah, blf + 2);
                mma16816(acc2[2*p+1], al, bhf + 2);
            }
            if (wh == 1) {   // v'[.,64]=1 (hi), lo=0 -> exact sum of k
                uint32_t dh[2];
                ldsm2t(dh, sb + SM_VHI + (uint32_t)(ks * 16) * LDBB + 128 + btoff);
                mma16816(accn, ah, dh);
                mma16816(accn, al, dh);
            }
        }
        __syncthreads();   // K/Q/V reads done before next phase A
    }

    // ---- Epilogue: merge new_kv / new_norm ---------------------------------
    float* kvo = dout + KV_OFF + (long long)bh * DE * DE;
    #pragma unroll
    for (int nb = 0; nb < 4; nb++) {
        int col = eoff + nb * 8 + tig * 2;
        atomicAdd(&kvo[(dR + g8) * DE + col],     acc2[nb][0]);
        atomicAdd(&kvo[(dR + g8) * DE + col + 1], acc2[nb][1]);
        atomicAdd(&kvo[(dR + g8 + 8) * DE + col],     acc2[nb][2]);
        atomicAdd(&kvo[(dR + g8 + 8) * DE + col + 1], acc2[nb][3]);
    }
    if (wh == 1 && tig == 0) {
        float* no = dout + NORM_OFF + (long long)bh * DE;
        atomicAdd(&no[dR + g8],     accn[0]);
        atomicAdd(&no[dR + g8 + 8], accn[2]);
    }
}

// ---------------------------------------------------------------------------
extern "C" void kernel_launch(void* const* d_in, const int* in_sizes, int n_in,
                              void* d_out, int out_size) {
    const float* keys    = (const float*)d_in[0];
    const float* values  = (const float*)d_in[1];
    const float* queries = (const float*)d_in[2];
    const float* outin   = (const float*)d_in[3];
    const float* pkv     = (const float*)d_in[4];
    const float* pnorm   = (const float*)d_in[5];
    const float* hg      = (const float*)d_in[6];
    float* dout = (float*)d_out;

    cudaFuncSetAttribute(fw_main, cudaFuncAttributeMaxDynamicSharedMemorySize,
                         SMEM_TOTAL);

    fw_init<<<(B_ * H_ * DE * DE + 255) / 256, 256>>>(pkv, pnorm, dout);

    dim3 grid(SPLIT, B_ * H_);
    fw_main<<<grid, 256, SMEM_TOTAL>>>(keys, values, queries, outin,
                                       pkv, pnorm, hg, dout);
}